// round 5
// baseline (speedup 1.0000x reference)
#include <cuda_runtime.h>

#define NPTS 262144
#define CCLS 10
#define DFEAT 64
#define TTRI 4096

#define NTHR 256
#define NBLK 512
#define ROWS_PER_BLK 512            // 512 * 512 = NPTS exact
#define MSE_PER_BLK 384             // 512 * 384 = 196608 = 3N/4 float4-pairs exact
#define CE_VEC4 (ROWS_PER_BLK * CCLS / 4)   // 1280 float4 per array per block

__global__ void __launch_bounds__(NTHR, 4) fused_loss_kernel(
    const float* __restrict__ gt_img,
    const float* __restrict__ gt_seg,
    const float* __restrict__ inr_output,
    const float* __restrict__ seg_output,
    const float* __restrict__ inr_features,
    const int* __restrict__ a_idx,
    const int* __restrict__ p_idx,
    const int* __restrict__ n_idx,
    float* __restrict__ out)
{
    __shared__ float sx[ROWS_PER_BLK * CCLS];   // 20 KB
    __shared__ float sg[ROWS_PER_BLK * CCLS];   // 20 KB

    const int tid  = threadIdx.x;
    const int bid  = blockIdx.x;
    const int lane = tid & 31;

    float acc = 0.0f;

    // ---------- MSE loads (4 x LDG.128, all independent) -------------------
    const float4* io4 = (const float4*)inr_output + bid * MSE_PER_BLK;
    const float4* gi4 = (const float4*)gt_img     + bid * MSE_PER_BLK;
    float4 ma0 = io4[tid];
    float4 mb0 = gi4[tid];
    float4 ma1, mb1;
    const bool dm1 = tid < (MSE_PER_BLK - NTHR);   // tid < 128
    if (dm1) { ma1 = io4[NTHR + tid]; mb1 = gi4[NTHR + tid]; }

    // ---------- Triplet loads (idx then 3 x LDG.64 gather) -----------------
    const int gw = bid * (NTHR / 32) + (tid >> 5);   // 0..4095, exact
    const int ia = a_idx[gw], ip = p_idx[gw], in_ = n_idx[gw];
    float2 av = ((const float2*)(inr_features + (size_t)ia * DFEAT))[lane];
    float2 pv = ((const float2*)(inr_features + (size_t)ip * DFEAT))[lane];
    float2 nv = ((const float2*)(inr_features + (size_t)in_ * DFEAT))[lane];

    // ---------- CE stage: global -> smem, pure float4 streams --------------
    {
        const float4* xs4 = (const float4*)seg_output + (size_t)bid * CE_VEC4;
        const float4* gs4 = (const float4*)gt_seg     + (size_t)bid * CE_VEC4;
        float4* smx = (float4*)sx;
        float4* smg = (float4*)sg;
        #pragma unroll
        for (int j = 0; j < CE_VEC4 / NTHR; j++) {      // 5 iters
            smx[tid + j * NTHR] = xs4[tid + j * NTHR];
            smg[tid + j * NTHR] = gs4[tid + j * NTHR];
        }
    }

    // ---------- MSE compute ------------------------------------------------
    {
        float mse = 0.0f, dx, dy, dz, dw;
        dx = ma0.x - mb0.x; dy = ma0.y - mb0.y; dz = ma0.z - mb0.z; dw = ma0.w - mb0.w;
        mse += dx * dx + dy * dy + dz * dz + dw * dw;
        if (dm1) {
            dx = ma1.x - mb1.x; dy = ma1.y - mb1.y; dz = ma1.z - mb1.z; dw = ma1.w - mb1.w;
            mse += dx * dx + dy * dy + dz * dz + dw * dw;
        }
        acc += mse * (1.0f / (float)(NPTS * 3));
    }

    // ---------- Triplet compute --------------------------------------------
    {
        float dpx = av.x - pv.x, dpy = av.y - pv.y;
        float dnx = av.x - nv.x, dny = av.y - nv.y;
        float dp = dpx * dpx + dpy * dpy;
        float dn = dnx * dnx + dny * dny;
        #pragma unroll
        for (int o = 16; o > 0; o >>= 1) {
            dp += __shfl_xor_sync(0xffffffff, dp, o);
            dn += __shfl_xor_sync(0xffffffff, dn, o);
        }
        if (lane == 0) acc += fmaxf(sqrtf(dp) - sqrtf(dn), 0.0f);
    }

    __syncthreads();

    // ---------- CE compute: 2 rows per thread from smem --------------------
    {
        float ce = 0.0f;
        #pragma unroll
        for (int r = 0; r < 2; r++) {
            const int row = tid + r * NTHR;
            const float2* x2 = (const float2*)(sx + row * CCLS);
            const float2* g2 = (const float2*)(sg + row * CCLS);
            float x[CCLS], g[CCLS];
            #pragma unroll
            for (int j = 0; j < CCLS / 2; j++) {
                float2 v = x2[j]; x[2 * j] = v.x; x[2 * j + 1] = v.y;
                float2 w = g2[j]; g[2 * j] = w.x; g[2 * j + 1] = w.y;
            }
            float m = x[0];
            #pragma unroll
            for (int c = 1; c < CCLS; c++) m = fmaxf(m, x[c]);
            float se = 0.0f, dot = 0.0f, gs = 0.0f;
            #pragma unroll
            for (int c = 0; c < CCLS; c++) {
                se  += __expf(x[c] - m);
                dot += g[c] * x[c];
                gs  += g[c];
            }
            float lse = __logf(se);
            ce += gs * (m + lse) - dot;   // = -sum_c g*(x - m - lse)
        }
        acc += ce * (1.0f / (float)NPTS);
    }

    // ---------- Block reduce + one atomic per block -------------------------
    __shared__ float sm[NTHR / 32];
    #pragma unroll
    for (int o = 16; o > 0; o >>= 1)
        acc += __shfl_xor_sync(0xffffffff, acc, o);
    const int wid = tid >> 5;
    if (lane == 0) sm[wid] = acc;
    __syncthreads();
    if (wid == 0) {
        float v = (lane < (NTHR >> 5)) ? sm[lane] : 0.0f;
        #pragma unroll
        for (int o = 16; o > 0; o >>= 1)
            v += __shfl_xor_sync(0xffffffff, v, o);
        if (lane == 0) atomicAdd(out, v);
    }
}

extern "C" void kernel_launch(void* const* d_in, const int* in_sizes, int n_in,
                              void* d_out, int out_size) {
    const float* gt_img       = (const float*)d_in[0];
    const float* gt_seg       = (const float*)d_in[1];
    const float* inr_output   = (const float*)d_in[2];
    const float* seg_output   = (const float*)d_in[3];
    const float* inr_features = (const float*)d_in[4];
    const int*   a_idx        = (const int*)d_in[5];
    const int*   p_idx        = (const int*)d_in[6];
    const int*   n_idx        = (const int*)d_in[7];
    float* out = (float*)d_out;

    cudaMemsetAsync(out, 0, sizeof(float));
    fused_loss_kernel<<<NBLK, NTHR>>>(gt_img, gt_seg, inr_output, seg_output,
                                      inr_features, a_idx, p_idx, n_idx, out);
}

// round 6
// speedup vs baseline: 1.1169x; 1.1169x over previous
#include <cuda_runtime.h>
#include <cstdint>

#define NPTS 262144
#define CCLS 10
#define DFEAT 64
#define TTRI 4096

#define NTHR 256
#define NBLK 1024
#define ROWS_PER_BLK 256                       // 1024 * 256 = NPTS exact
#define CE_BYTES (ROWS_PER_BLK * CCLS * 4)     // 10240 B per array per block
#define MSE_PER_BLK 192                        // 1024 * 192 = 196608 = 3N/4 exact

__device__ __forceinline__ uint32_t smem_u32(const void* p) {
    uint32_t a;
    asm("{ .reg .u64 t; cvta.to.shared.u64 t, %1; cvt.u32.u64 %0, t; }"
        : "=r"(a) : "l"(p));
    return a;
}

__global__ void __launch_bounds__(NTHR) fused_loss_kernel(
    const float* __restrict__ gt_img,
    const float* __restrict__ gt_seg,
    const float* __restrict__ inr_output,
    const float* __restrict__ seg_output,
    const float* __restrict__ inr_features,
    const int* __restrict__ a_idx,
    const int* __restrict__ p_idx,
    const int* __restrict__ n_idx,
    float* __restrict__ out)
{
    __shared__ alignas(128) float sx[ROWS_PER_BLK * CCLS];   // 10 KB
    __shared__ alignas(128) float sg[ROWS_PER_BLK * CCLS];   // 10 KB
    __shared__ alignas(8) unsigned long long mbar;

    const int tid  = threadIdx.x;
    const int bid  = blockIdx.x;
    const int lane = tid & 31;
    const uint32_t mb = smem_u32(&mbar);

    // ---- mbarrier init ----------------------------------------------------
    if (tid == 0) {
        asm volatile("mbarrier.init.shared::cta.b64 [%0], 1;" :: "r"(mb) : "memory");
    }
    __syncthreads();

    // ---- issue bulk async copies for the CE streams (single thread) -------
    if (tid == 0) {
        asm volatile("mbarrier.arrive.expect_tx.shared::cta.b64 _, [%0], %1;"
                     :: "r"(mb), "r"(2 * CE_BYTES) : "memory");
        const char* gx = (const char*)seg_output + (size_t)bid * CE_BYTES;
        const char* gg = (const char*)gt_seg     + (size_t)bid * CE_BYTES;
        asm volatile(
            "cp.async.bulk.shared::cta.global.mbarrier::complete_tx::bytes "
            "[%0], [%1], %2, [%3];"
            :: "r"(smem_u32(sx)), "l"(gx), "r"(CE_BYTES), "r"(mb) : "memory");
        asm volatile(
            "cp.async.bulk.shared::cta.global.mbarrier::complete_tx::bytes "
            "[%0], [%1], %2, [%3];"
            :: "r"(smem_u32(sg)), "l"(gg), "r"(CE_BYTES), "r"(mb) : "memory");
    }

    float acc = 0.0f;

    // ---- MSE via LDG (overlaps with bulk copies) --------------------------
    if (tid < MSE_PER_BLK) {
        const float4* io4 = (const float4*)inr_output + bid * MSE_PER_BLK;
        const float4* gi4 = (const float4*)gt_img     + bid * MSE_PER_BLK;
        float4 a = io4[tid];
        float4 b = gi4[tid];
        float dx = a.x - b.x, dy = a.y - b.y, dz = a.z - b.z, dw = a.w - b.w;
        acc += (dx * dx + dy * dy + dz * dz + dw * dw)
             * (1.0f / (float)(NPTS * 3));
    }

    // ---- Triplet: warp per triplet (first 4096 global warps) --------------
    {
        const int gw = bid * (NTHR / 32) + (tid >> 5);   // 0..8191
        if (gw < TTRI) {
            const int ia = a_idx[gw], ip = p_idx[gw], in_ = n_idx[gw];
            float2 av = ((const float2*)(inr_features + (size_t)ia * DFEAT))[lane];
            float2 pv = ((const float2*)(inr_features + (size_t)ip * DFEAT))[lane];
            float2 nv = ((const float2*)(inr_features + (size_t)in_ * DFEAT))[lane];
            float dpx = av.x - pv.x, dpy = av.y - pv.y;
            float dnx = av.x - nv.x, dny = av.y - nv.y;
            float dp = dpx * dpx + dpy * dpy;
            float dn = dnx * dnx + dny * dny;
            #pragma unroll
            for (int o = 16; o > 0; o >>= 1) {
                dp += __shfl_xor_sync(0xffffffff, dp, o);
                dn += __shfl_xor_sync(0xffffffff, dn, o);
            }
            if (lane == 0) acc += fmaxf(sqrtf(dp) - sqrtf(dn), 0.0f);
        }
    }

    // ---- wait for bulk copies (acquire) -----------------------------------
    asm volatile(
        "{\n\t"
        ".reg .pred P;\n"
        "W%=:\n\t"
        "mbarrier.try_wait.parity.acquire.cta.shared::cta.b64 P, [%0], 0;\n\t"
        "@!P bra W%=;\n\t"
        "}"
        :: "r"(mb) : "memory");

    // ---- CE compute: one row per thread from smem -------------------------
    {
        const float2* x2 = (const float2*)(sx + tid * CCLS);
        const float2* g2 = (const float2*)(sg + tid * CCLS);
        float x[CCLS], g[CCLS];
        #pragma unroll
        for (int j = 0; j < CCLS / 2; j++) {
            float2 v = x2[j]; x[2 * j] = v.x; x[2 * j + 1] = v.y;
            float2 w = g2[j]; g[2 * j] = w.x; g[2 * j + 1] = w.y;
        }
        float m = x[0];
        #pragma unroll
        for (int c = 1; c < CCLS; c++) m = fmaxf(m, x[c]);
        float se = 0.0f, dot = 0.0f, gs = 0.0f;
        #pragma unroll
        for (int c = 0; c < CCLS; c++) {
            se  += __expf(x[c] - m);
            dot += g[c] * x[c];
            gs  += g[c];
        }
        float lse = __logf(se);
        acc += (gs * (m + lse) - dot) * (1.0f / (float)NPTS);
    }

    // ---- Block reduce + one atomic per block ------------------------------
    __shared__ float sm[NTHR / 32];
    #pragma unroll
    for (int o = 16; o > 0; o >>= 1)
        acc += __shfl_xor_sync(0xffffffff, acc, o);
    const int wid = tid >> 5;
    if (lane == 0) sm[wid] = acc;
    __syncthreads();
    if (wid == 0) {
        float v = (lane < (NTHR >> 5)) ? sm[lane] : 0.0f;
        #pragma unroll
        for (int o = 16; o > 0; o >>= 1)
            v += __shfl_xor_sync(0xffffffff, v, o);
        if (lane == 0) atomicAdd(out, v);
    }
}

extern "C" void kernel_launch(void* const* d_in, const int* in_sizes, int n_in,
                              void* d_out, int out_size) {
    const float* gt_img       = (const float*)d_in[0];
    const float* gt_seg       = (const float*)d_in[1];
    const float* inr_output   = (const float*)d_in[2];
    const float* seg_output   = (const float*)d_in[3];
    const float* inr_features = (const float*)d_in[4];
    const int*   a_idx        = (const int*)d_in[5];
    const int*   p_idx        = (const int*)d_in[6];
    const int*   n_idx        = (const int*)d_in[7];
    float* out = (float*)d_out;

    cudaMemsetAsync(out, 0, sizeof(float));
    fused_loss_kernel<<<NBLK, NTHR>>>(gt_img, gt_seg, inr_output, seg_output,
                                      inr_features, a_idx, p_idx, n_idx, out);
}